// round 13
// baseline (speedup 1.0000x reference)
#include <cuda_runtime.h>
#include <cuda_fp16.h>
#include <math.h>
#include <stdint.h>

#define BB 32
#define NN 512
#define HH 128

// h as single f16 plane, [b][d][n] (transposed), row-contiguous in n. 4 MB.
__device__ __half g_hB[BB * HH * NN];
// K1->K2 readiness counters, one per batch; reset via cudaMemsetAsync per call.
__device__ int g_sync[BB];

__device__ __forceinline__ uint32_t smem_u32(const void* p) {
    uint32_t a;
    asm("{ .reg .u64 t; cvta.to.shared.u64 t, %1; cvt.u32.u64 %0, t; }"
        : "=r"(a) : "l"(p));
    return a;
}

#define CP_ASYNC16(dst_u32, src_ptr) \
    asm volatile("cp.async.cg.shared.global [%0], [%1], 16;" \
                 :: "r"(dst_u32), "l"(src_ptr) : "memory")
#define CP_COMMIT() asm volatile("cp.async.commit_group;" ::: "memory")
#define CP_WAIT(n)  asm volatile("cp.async.wait_group %0;" :: "n"(n) : "memory")

#define LDSM_X4(r, addr) \
    asm volatile("ldmatrix.sync.aligned.m8n8.x4.shared.b16 {%0,%1,%2,%3}, [%4];" \
                 : "=r"((r)[0]), "=r"((r)[1]), "=r"((r)[2]), "=r"((r)[3]) \
                 : "r"(addr))

#define MMA_F16(acc, a, b0, b1) \
    asm volatile("mma.sync.aligned.m16n8k16.row.col.f32.f16.f16.f32 " \
                 "{%0,%1,%2,%3}, {%4,%5,%6,%7}, {%8,%9}, {%0,%1,%2,%3};" \
                 : "+f"((acc)[0]), "+f"((acc)[1]), "+f"((acc)[2]), "+f"((acc)[3]) \
                 : "r"((a)[0]), "r"((a)[1]), "r"((a)[2]), "r"((a)[3]), \
                   "r"(b0), "r"(b1))

// ---------------------------------------------------------------------------
// K1 smem overlays (104448 B total):
//   WHI f16 [128 d][272B] @0      (34816)  -- TR u32[128][66] overlays after MMA
//   WLO f16 [128 d][272B] @34816  (34816)
//   SHI f16 [64 n][272B]  @69632  (17408)  -- HP f32[64][132] overlays after MMA
//   SLO f16 [64 n][272B]  @87040  (17408)
// K2 smem (92160 B): A[2][3c][2sp][32 i][144B] (55296) | B[2][128 d][144B] @55296
// ---------------------------------------------------------------------------
#define K1_ROWB 272
#define K1_WHI  0
#define K1_WLO  34816
#define K1_SHI  69632
#define K1_SLO  87040
#define K1_HP   69632
#define K1_TR   0

#define A_BUF_STRIDE 27648
#define A_C_STRIDE   9216
#define A_S_STRIDE   4608
#define SM_ROW       144
#define B_BASE       55296
#define B_BUF_STRIDE 18432

#define FUSED_SMEM   104448

__global__ void __launch_bounds__(256, 2)
k_fused(const float* __restrict__ s,
        const float* __restrict__ W1,
        const float* __restrict__ b1,
        const float* __restrict__ ev,
        const float* __restrict__ mask,
        float* __restrict__ out) {
    extern __shared__ char smc[];
    const uint32_t smem_base = smem_u32(smc);
    const int t    = threadIdx.x;
    const int lane = t & 31;
    const int wid  = t >> 5;

    if (blockIdx.x < 256) {
        // ================= K1 path: h = silu(LN(s @ W1^T + b1)) =============
        const int bid  = blockIdx.x;
        const int wm   = wid >> 1;     // 0..3: row subtile of 16
        const int wn   = wid & 1;      // 0..1: d subtile of 64
        const int row0 = bid * 64;
        const int b    = bid >> 3;
        const int n0   = (bid & 7) * 64;

        // ---- convert W1 fp32 -> f16 hi/lo planes (direct from global)
#pragma unroll
        for (int k = 0; k < 32; ++k) {
            int u = t + k * 256;           // pair index 0..8191
            int d = u >> 6, kp = u & 63;
            float2 v = *(const float2*)&W1[u * 2];
            __half h0 = __float2half_rn(v.x), h1 = __float2half_rn(v.y);
            __half l0 = __float2half_rn(v.x - __half2float(h0));
            __half l1 = __float2half_rn(v.y - __half2float(h1));
            *(uint32_t*)(smc + K1_WHI + d * K1_ROWB + kp * 4) =
                (uint32_t)__half_as_ushort(h0) | ((uint32_t)__half_as_ushort(h1) << 16);
            *(uint32_t*)(smc + K1_WLO + d * K1_ROWB + kp * 4) =
                (uint32_t)__half_as_ushort(l0) | ((uint32_t)__half_as_ushort(l1) << 16);
        }
        // ---- convert s tile fp32 -> f16 hi/lo planes
#pragma unroll
        for (int k = 0; k < 16; ++k) {
            int u = t + k * 256;           // pair index 0..4095
            int r = u >> 6, kp = u & 63;
            float2 v = *(const float2*)&s[(size_t)row0 * 128 + u * 2];
            __half h0 = __float2half_rn(v.x), h1 = __float2half_rn(v.y);
            __half l0 = __float2half_rn(v.x - __half2float(h0));
            __half l1 = __float2half_rn(v.y - __half2float(h1));
            *(uint32_t*)(smc + K1_SHI + r * K1_ROWB + kp * 4) =
                (uint32_t)__half_as_ushort(h0) | ((uint32_t)__half_as_ushort(h1) << 16);
            *(uint32_t*)(smc + K1_SLO + r * K1_ROWB + kp * 4) =
                (uint32_t)__half_as_ushort(l0) | ((uint32_t)__half_as_ushort(l1) << 16);
        }
        __syncthreads();

        // ---- MMA: warp tile m16 x n64, K=128 over 8 kb-steps, 3 passes
        float acc[8][4];
#pragma unroll
        for (int nt = 0; nt < 8; ++nt)
#pragma unroll
            for (int q = 0; q < 4; ++q) acc[nt][q] = 0.0f;

        const uint32_t aaddr = smem_base + K1_SHI
            + (uint32_t)((wm * 16 + (lane & 15)) * K1_ROWB + (lane >> 4) * 16);
        uint32_t baddr[4];
#pragma unroll
        for (int q = 0; q < 4; ++q) {
            int n = wn * 64 + q * 16 + (lane & 7) + ((lane >> 4) & 1) * 8;
            baddr[q] = smem_base + K1_WHI
                + (uint32_t)(n * K1_ROWB + ((lane >> 3) & 1) * 16);
        }

#pragma unroll
        for (int kb = 0; kb < 8; ++kb) {
            uint32_t afr[2][4];
            LDSM_X4(afr[0], aaddr + kb * 32);
            LDSM_X4(afr[1], aaddr + (K1_SLO - K1_SHI) + kb * 32);
            uint32_t bfr[2][4][4];
#pragma unroll
            for (int sp = 0; sp < 2; ++sp)
#pragma unroll
                for (int q = 0; q < 4; ++q)
                    LDSM_X4(bfr[sp][q], baddr[q] + sp * (K1_WLO - K1_WHI) + kb * 32);
#pragma unroll
            for (int pass = 0; pass < 3; ++pass) {
                const int as = (pass == 1) ? 1 : 0;
                const int bs = (pass == 2) ? 1 : 0;
#pragma unroll
                for (int nt = 0; nt < 8; ++nt) {
                    uint32_t* bbv = bfr[bs][nt >> 1];
                    MMA_F16(acc[nt], afr[as],
                            bbv[(nt & 1) * 2], bbv[(nt & 1) * 2 + 1]);
                }
            }
        }
        __syncthreads();           // all LDSM of s/W planes done

        // ---- fragments (+bias from global) -> HP (overlays SHI/SLO)
        float* hpf = (float*)(smc + K1_HP);
        {
            int r = wm * 16 + (lane >> 2);
#pragma unroll
            for (int nt = 0; nt < 8; ++nt) {
                int d = wn * 64 + (nt >> 1) * 16 + (nt & 1) * 8 + (lane & 3) * 2;
                float2 bb = *(const float2*)&b1[d];
                *(float2*)&hpf[r * 132 + d] =
                    make_float2(acc[nt][0] + bb.x, acc[nt][1] + bb.y);
                *(float2*)&hpf[(r + 8) * 132 + d] =
                    make_float2(acc[nt][2] + bb.x, acc[nt][3] + bb.y);
            }
        }
        __syncthreads();

        // ---- LN + SiLU + f16 -> TR (overlays WHI)
        uint32_t* tr = (uint32_t*)(smc + K1_TR);
        const float inv128 = 1.0f / 128.0f;
        const float4* hp4 = (const float4*)hpf;
#pragma unroll
        for (int rr = 0; rr < 8; ++rr) {
            int row = wid * 8 + rr;
            float4 x = hp4[row * 33 + lane];
            float sm = x.x + x.y + x.z + x.w;
            float sq = x.x * x.x + x.y * x.y + x.z * x.z + x.w * x.w;
#pragma unroll
            for (int o = 16; o > 0; o >>= 1) {
                sm += __shfl_xor_sync(0xFFFFFFFFu, sm, o);
                sq += __shfl_xor_sync(0xFFFFFFFFu, sq, o);
            }
            float mu  = sm * inv128;
            float var = sq * inv128 - mu * mu;
            float rs  = rsqrtf(var + 1e-5f);
            float y[4];
            y[0] = (x.x - mu) * rs; y[1] = (x.y - mu) * rs;
            y[2] = (x.z - mu) * rs; y[3] = (x.w - mu) * rs;
#pragma unroll
            for (int q = 0; q < 4; ++q) {
                float yv = y[q] / (1.0f + __expf(-y[q]));    // silu
                tr[(4 * lane + q) * 66 + row] =
                    (uint32_t)__half_as_ushort(__float2half_rn(yv));
            }
        }
        __syncthreads();

        // ---- packed transposed store -> g_hB
#pragma unroll
        for (int k = 0; k < 16; ++k) {
            int u = t + k * 256;              // 0..4095
            int d = u >> 5, np = u & 31;
            uint2 tp = *(uint2*)&tr[d * 66 + 2 * np];
            uint32_t pk = (tp.x & 0xFFFFu) | (tp.y << 16);
            ((uint32_t*)g_hB)[((b * 128 + d) * 512 + n0) / 2 + np] = pk;
        }

        // ---- release: stores visible, then signal
        __threadfence();
        __syncthreads();
        if (t == 0) atomicAdd(&g_sync[b], 1);

    } else {
        // ================= K2 path: CFConv via f16-split HMMA ================
        const int bid  = blockIdx.x - 256;
        const int wm   = wid >> 2;     // 0..1: i-subtile of 16
        const int wn   = wid & 3;      // 0..3: d-subtile of 32
        const int b    = bid >> 4;
        const int i0   = (bid & 15) * 32;

        const int cv_i  = t >> 3;      // 0..31
        const int cv_jb = t & 7;
        const float* ev_row = ev + ((size_t)((b * 512 + i0 + cv_i) * 512)) * 3 + cv_jb * 24;
        const float* mk_row = mask + (size_t)(b * 512 + i0 + cv_i) * 512 + cv_jb * 8;
        const uint32_t cv_dst = (uint32_t)(cv_i * SM_ROW + cv_jb * 16);

        float acc[3][4][4];
#pragma unroll
        for (int c = 0; c < 3; ++c)
#pragma unroll
            for (int nt = 0; nt < 4; ++nt)
#pragma unroll
                for (int q = 0; q < 4; ++q) acc[c][nt][q] = 0.0f;

        const uint32_t a_lane = (uint32_t)((wm * 16 + (lane & 15)) * SM_ROW + (lane >> 4) * 16);
        uint32_t b_lane[2];
#pragma unroll
        for (int q = 0; q < 2; ++q) {
            int n = wn * 32 + q * 16 + (lane & 7) + ((lane >> 4) & 1) * 8;
            b_lane[q] = (uint32_t)(B_BASE + n * SM_ROW + ((lane >> 3) & 1) * 16);
        }

        auto issue_B = [&](int j0, int pb) {
#pragma unroll
            for (int p = t; p < 1024; p += 256) {
                int d = p >> 3, q = p & 7;
                const char* src = (const char*)g_hB
                    + ((size_t)((b * 128 + d) * 512 + j0) * 2) + q * 16;
                CP_ASYNC16(smem_base + B_BASE + pb * B_BUF_STRIDE + d * SM_ROW + q * 16, src);
            }
            CP_COMMIT();
        };

        auto ldg_half = [&](int j0, int h, float4* rev, float4& rmk) {
            const float4* ep = (const float4*)(ev_row + (size_t)j0 * 3 + h * 12);
            rev[0] = ep[0]; rev[1] = ep[1]; rev[2] = ep[2];
            rmk = *(const float4*)(mk_row + j0 + h * 4);
        };

        auto convert_half = [&](int pa, int h, const float4* rev, const float4& rmk) {
            const float* evv = (const float*)rev;   // 12 floats: [j][c]
            float mv[4] = {rmk.x, rmk.y, rmk.z, rmk.w};
#pragma unroll
            for (int c = 0; c < 3; ++c) {
                uint32_t hi2[2], lo2[2];
#pragma unroll
                for (int pr = 0; pr < 2; ++pr) {
                    float v0 = evv[(2 * pr)     * 3 + c] * mv[2 * pr];
                    float v1 = evv[(2 * pr + 1) * 3 + c] * mv[2 * pr + 1];
                    __half h0 = __float2half_rn(v0);
                    __half h1 = __float2half_rn(v1);
                    __half l0 = __float2half_rn(v0 - __half2float(h0));
                    __half l1 = __float2half_rn(v1 - __half2float(h1));
                    hi2[pr] = (uint32_t)__half_as_ushort(h0)
                            | ((uint32_t)__half_as_ushort(h1) << 16);
                    lo2[pr] = (uint32_t)__half_as_ushort(l0)
                            | ((uint32_t)__half_as_ushort(l1) << 16);
                }
                char* dst = smc + pa * A_BUF_STRIDE + c * A_C_STRIDE + cv_dst + h * 8;
                *(uint2*)dst                = make_uint2(hi2[0], hi2[1]);
                *(uint2*)(dst + A_S_STRIDE) = make_uint2(lo2[0], lo2[1]);
            }
        };

        auto mma_kb = [&](int kb, int pa, int pb) {
            uint32_t afr[3][2][4];
            uint32_t bfr[2][4];
#pragma unroll
            for (int c = 0; c < 3; ++c)
#pragma unroll
                for (int sp = 0; sp < 2; ++sp)
                    LDSM_X4(afr[c][sp], smem_base + pa * A_BUF_STRIDE + c * A_C_STRIDE
                                      + sp * A_S_STRIDE + a_lane + kb * 32);
#pragma unroll
            for (int q = 0; q < 2; ++q)
                LDSM_X4(bfr[q], smem_base + b_lane[q] + pb * B_BUF_STRIDE + kb * 32);
#pragma unroll
            for (int pass = 0; pass < 2; ++pass) {
#pragma unroll
                for (int c = 0; c < 3; ++c)
#pragma unroll
                    for (int nt = 0; nt < 4; ++nt) {
                        uint32_t* bbv = bfr[nt >> 1];
                        MMA_F16(acc[c][nt], afr[c][pass],
                                bbv[(nt & 1) * 2], bbv[(nt & 1) * 2 + 1]);
                    }
            }
        };

        // ---- prologue: A(0) fill is K1-independent — do it BEFORE the wait
        {
            float4 rev[3]; float4 rmk;
            ldg_half(0, 0, rev, rmk);
            convert_half(0, 0, rev, rmk);
            ldg_half(0, 1, rev, rmk);
            convert_half(0, 1, rev, rmk);
        }
        // ---- wait for this batch's h (8 K1 CTAs)
        if (t == 0) {
            while (*(volatile int*)&g_sync[b] < 8) __nanosleep(64);
            __threadfence();
        }
        __syncthreads();
        issue_B(0, 0);
        CP_WAIT(0);
        __syncthreads();

#pragma unroll 1
        for (int ch = 0; ch < 8; ++ch) {
            const int p  = ch & 1;
            const int np = p ^ 1;
            const int nj = (ch + 1) * 64;
            float4 rev[3]; float4 rmk;

            if (ch < 7) {
                issue_B(nj, np);
                ldg_half(nj, 0, rev, rmk);
            }
            mma_kb(0, p, p);
            mma_kb(1, p, p);
            if (ch < 7) {
                convert_half(np, 0, rev, rmk);
                ldg_half(nj, 1, rev, rmk);
            }
            mma_kb(2, p, p);
            mma_kb(3, p, p);
            if (ch < 7) {
                convert_half(np, 1, rev, rmk);
            }
            CP_WAIT(0);
            __syncthreads();
        }

        // ---- epilogue: fragments -> out[b][i][c][d]
        const int r0 = i0 + wm * 16 + (lane >> 2);
        const int dq = wn * 32 + (lane & 3) * 2;
#pragma unroll
        for (int c = 0; c < 3; ++c) {
#pragma unroll
            for (int nt = 0; nt < 4; ++nt) {
                int d = dq + nt * 8;
                size_t o0 = ((size_t)(b * 512 + r0)     * 3 + c) * 128 + d;
                size_t o1 = ((size_t)(b * 512 + r0 + 8) * 3 + c) * 128 + d;
                *(float2*)(out + o0) = make_float2(acc[c][nt][0], acc[c][nt][1]);
                *(float2*)(out + o1) = make_float2(acc[c][nt][2], acc[c][nt][3]);
            }
        }
    }
}

// ---------------------------------------------------------------------------
extern "C" void kernel_launch(void* const* d_in, const int* in_sizes, int n_in,
                              void* d_out, int out_size) {
    const float* s    = (const float*)d_in[0];   // (32,512,128)
    const float* ev   = (const float*)d_in[1];   // (32,512,512,3)
    const float* mask = (const float*)d_in[2];   // (32,512,512,1)
    const float* W1   = (const float*)d_in[3];   // (128,128)
    const float* b1   = (const float*)d_in[4];   // (128,)
    float* out = (float*)d_out;                  // (32,512,3,128)

    // reset readiness counters each call (graph-capturable memset node)
    void* sync_ptr = nullptr;
    cudaGetSymbolAddress(&sync_ptr, g_sync);
    cudaMemsetAsync(sync_ptr, 0, BB * sizeof(int));

    cudaFuncSetAttribute(k_fused,
                         cudaFuncAttributeMaxDynamicSharedMemorySize, FUSED_SMEM);
    k_fused<<<256 + BB * 16, 256, FUSED_SMEM>>>(s, W1, b1, ev, mask, out);
}

// round 14
// speedup vs baseline: 1.2688x; 1.2688x over previous
#include <cuda_runtime.h>
#include <cuda_fp16.h>
#include <math.h>
#include <stdint.h>

#define BB 32
#define NN 512
#define HH 128

// h as single f16 plane, [b][d][n] (transposed), row-contiguous in n. 4 MB.
__device__ __half g_hB[BB * HH * NN];

__device__ __forceinline__ uint32_t smem_u32(const void* p) {
    uint32_t a;
    asm("{ .reg .u64 t; cvta.to.shared.u64 t, %1; cvt.u32.u64 %0, t; }"
        : "=r"(a) : "l"(p));
    return a;
}

#define CP_ASYNC16(dst_u32, src_ptr) \
    asm volatile("cp.async.cg.shared.global [%0], [%1], 16;" \
                 :: "r"(dst_u32), "l"(src_ptr) : "memory")
#define CP_COMMIT() asm volatile("cp.async.commit_group;" ::: "memory")
#define CP_WAIT(n)  asm volatile("cp.async.wait_group %0;" :: "n"(n) : "memory")

#define LDSM_X4(r, addr) \
    asm volatile("ldmatrix.sync.aligned.m8n8.x4.shared.b16 {%0,%1,%2,%3}, [%4];" \
                 : "=r"((r)[0]), "=r"((r)[1]), "=r"((r)[2]), "=r"((r)[3]) \
                 : "r"(addr))

#define MMA_F16(acc, a, b0, b1) \
    asm volatile("mma.sync.aligned.m16n8k16.row.col.f32.f16.f16.f32 " \
                 "{%0,%1,%2,%3}, {%4,%5,%6,%7}, {%8,%9}, {%0,%1,%2,%3};" \
                 : "+f"((acc)[0]), "+f"((acc)[1]), "+f"((acc)[2]), "+f"((acc)[3]) \
                 : "r"((a)[0]), "r"((a)[1]), "r"((a)[2]), "r"((a)[3]), \
                   "r"(b0), "r"(b1))

// ---------------------------------------------------------------------------
// K1: h = silu(LN(s @ W1^T + b1)) via 3-pass split-f16 HMMA.
// 256 CTAs x 256 thr (8 warps, 4m x 2n); 64 rows/CTA; 2 CTAs/SM.
// W1 read + split directly from global (L2-hot). smem overlays (104448 B):
//   WHI f16 [128 d][272B] @0      -- TR u32[128][66] overlays after MMA
//   WLO f16 [128 d][272B] @34816
//   SHI f16 [64 n][272B]  @69632  -- HP f32[64][132] overlays after MMA
//   SLO f16 [64 n][272B]  @87040
// ---------------------------------------------------------------------------
#define K1_ROWB 272
#define K1_WHI  0
#define K1_WLO  34816
#define K1_SHI  69632
#define K1_SLO  87040
#define K1_HP   69632
#define K1_TR   0
#define K1_SMEM 104448

__global__ void __launch_bounds__(256, 2)
k1_lin_ln_silu(const float* __restrict__ s,
               const float* __restrict__ W1,
               const float* __restrict__ b1) {
    extern __shared__ char smc[];
    const uint32_t smem_base = smem_u32(smc);
    const int t    = threadIdx.x;
    const int lane = t & 31;
    const int wid  = t >> 5;
    const int wm   = wid >> 1;     // 0..3: row subtile of 16
    const int wn   = wid & 1;      // 0..1: d subtile of 64
    const int row0 = blockIdx.x * 64;
    const int b    = blockIdx.x >> 3;
    const int n0   = (blockIdx.x & 7) * 64;

    // ---- convert W1 fp32 -> f16 hi/lo planes (direct from global)
#pragma unroll
    for (int k = 0; k < 32; ++k) {
        int u = t + k * 256;           // pair index 0..8191
        int d = u >> 6, kp = u & 63;
        float2 v = *(const float2*)&W1[u * 2];
        __half h0 = __float2half_rn(v.x), h1 = __float2half_rn(v.y);
        __half l0 = __float2half_rn(v.x - __half2float(h0));
        __half l1 = __float2half_rn(v.y - __half2float(h1));
        *(uint32_t*)(smc + K1_WHI + d * K1_ROWB + kp * 4) =
            (uint32_t)__half_as_ushort(h0) | ((uint32_t)__half_as_ushort(h1) << 16);
        *(uint32_t*)(smc + K1_WLO + d * K1_ROWB + kp * 4) =
            (uint32_t)__half_as_ushort(l0) | ((uint32_t)__half_as_ushort(l1) << 16);
    }
    // ---- convert s tile fp32 -> f16 hi/lo planes
#pragma unroll
    for (int k = 0; k < 16; ++k) {
        int u = t + k * 256;           // pair index 0..4095
        int r = u >> 6, kp = u & 63;
        float2 v = *(const float2*)&s[(size_t)row0 * 128 + u * 2];
        __half h0 = __float2half_rn(v.x), h1 = __float2half_rn(v.y);
        __half l0 = __float2half_rn(v.x - __half2float(h0));
        __half l1 = __float2half_rn(v.y - __half2float(h1));
        *(uint32_t*)(smc + K1_SHI + r * K1_ROWB + kp * 4) =
            (uint32_t)__half_as_ushort(h0) | ((uint32_t)__half_as_ushort(h1) << 16);
        *(uint32_t*)(smc + K1_SLO + r * K1_ROWB + kp * 4) =
            (uint32_t)__half_as_ushort(l0) | ((uint32_t)__half_as_ushort(l1) << 16);
    }
    __syncthreads();

    // ---- MMA: warp tile m16 x n64, K=128 over 8 kb-steps, 3 passes
    float acc[8][4];
#pragma unroll
    for (int nt = 0; nt < 8; ++nt)
#pragma unroll
        for (int q = 0; q < 4; ++q) acc[nt][q] = 0.0f;

    const uint32_t aaddr = smem_base + K1_SHI
        + (uint32_t)((wm * 16 + (lane & 15)) * K1_ROWB + (lane >> 4) * 16);
    uint32_t baddr[4];
#pragma unroll
    for (int q = 0; q < 4; ++q) {
        int n = wn * 64 + q * 16 + (lane & 7) + ((lane >> 4) & 1) * 8;
        baddr[q] = smem_base + K1_WHI
            + (uint32_t)(n * K1_ROWB + ((lane >> 3) & 1) * 16);
    }

#pragma unroll
    for (int kb = 0; kb < 8; ++kb) {
        uint32_t afr[2][4];
        LDSM_X4(afr[0], aaddr + kb * 32);                    // s hi
        LDSM_X4(afr[1], aaddr + (K1_SLO - K1_SHI) + kb * 32);// s lo
        uint32_t bfr[2][4][4];
#pragma unroll
        for (int sp = 0; sp < 2; ++sp)
#pragma unroll
            for (int q = 0; q < 4; ++q)
                LDSM_X4(bfr[sp][q], baddr[q] + sp * (K1_WLO - K1_WHI) + kb * 32);
#pragma unroll
        for (int pass = 0; pass < 3; ++pass) {
            const int as = (pass == 1) ? 1 : 0;
            const int bs = (pass == 2) ? 1 : 0;
#pragma unroll
            for (int nt = 0; nt < 8; ++nt) {
                uint32_t* bbv = bfr[bs][nt >> 1];
                MMA_F16(acc[nt], afr[as],
                        bbv[(nt & 1) * 2], bbv[(nt & 1) * 2 + 1]);
            }
        }
    }
    __syncthreads();           // all LDSM of s/W planes done

    // ---- fragments (+bias from global) -> HP (overlays SHI/SLO)
    float* hpf = (float*)(smc + K1_HP);
    {
        int r = wm * 16 + (lane >> 2);
#pragma unroll
        for (int nt = 0; nt < 8; ++nt) {
            int d = wn * 64 + (nt >> 1) * 16 + (nt & 1) * 8 + (lane & 3) * 2;
            float2 bb = *(const float2*)&b1[d];
            *(float2*)&hpf[r * 132 + d] =
                make_float2(acc[nt][0] + bb.x, acc[nt][1] + bb.y);
            *(float2*)&hpf[(r + 8) * 132 + d] =
                make_float2(acc[nt][2] + bb.x, acc[nt][3] + bb.y);
        }
    }
    __syncthreads();

    // ---- LN + SiLU + f16 -> TR (overlays WHI)
    uint32_t* tr = (uint32_t*)(smc + K1_TR);
    const float inv128 = 1.0f / 128.0f;
    const float4* hp4 = (const float4*)hpf;
#pragma unroll
    for (int rr = 0; rr < 8; ++rr) {
        int row = wid * 8 + rr;
        float4 x = hp4[row * 33 + lane];
        float sm = x.x + x.y + x.z + x.w;
        float sq = x.x * x.x + x.y * x.y + x.z * x.z + x.w * x.w;
#pragma unroll
        for (int o = 16; o > 0; o >>= 1) {
            sm += __shfl_xor_sync(0xFFFFFFFFu, sm, o);
            sq += __shfl_xor_sync(0xFFFFFFFFu, sq, o);
        }
        float mu  = sm * inv128;
        float var = sq * inv128 - mu * mu;
        float rs  = rsqrtf(var + 1e-5f);
        float y[4];
        y[0] = (x.x - mu) * rs; y[1] = (x.y - mu) * rs;
        y[2] = (x.z - mu) * rs; y[3] = (x.w - mu) * rs;
#pragma unroll
        for (int q = 0; q < 4; ++q) {
            float yv = y[q] / (1.0f + __expf(-y[q]));    // silu
            tr[(4 * lane + q) * 66 + row] =
                (uint32_t)__half_as_ushort(__float2half_rn(yv));
        }
    }
    __syncthreads();

    // ---- packed transposed store -> g_hB
#pragma unroll
    for (int k = 0; k < 16; ++k) {
        int u = t + k * 256;              // 0..4095
        int d = u >> 5, np = u & 31;
        uint2 tp = *(uint2*)&tr[d * 66 + 2 * np];
        uint32_t pk = (tp.x & 0xFFFFu) | (tp.y << 16);
        ((uint32_t*)g_hB)[((b * 128 + d) * 512 + n0) / 2 + np] = pk;
    }
}

// ---------------------------------------------------------------------------
// K2 (R12, measured fastest): fully-overlapped f16-split HMMA CFConv, 2 CTAs/SM.
// grid: 32 b x 16 i-tiles (32 i) = 512 CTAs, 256 threads (8 warps 2m x 4n).
// smem (92160 B/CTA): A[2buf][3c][2sp][32 i][144B] (55296) | B[2buf][128 d][144B]
// ---------------------------------------------------------------------------
#define A_BUF_STRIDE 27648
#define A_C_STRIDE   9216
#define A_S_STRIDE   4608
#define SM_ROW       144
#define B_BASE       55296
#define B_BUF_STRIDE 18432
#define K2_SMEM      92160

__global__ void __launch_bounds__(256, 2)
k2_cfconv_mma(const float* __restrict__ ev,
              const float* __restrict__ mask,
              float* __restrict__ out) {
    extern __shared__ char smc[];
    const uint32_t smem_base = smem_u32(smc);
    const int t    = threadIdx.x;
    const int lane = t & 31;
    const int wid  = t >> 5;
    const int wm   = wid >> 2;     // 0..1: i-subtile of 16
    const int wn   = wid & 3;      // 0..3: d-subtile of 32
    const int b    = blockIdx.x >> 4;
    const int i0   = (blockIdx.x & 15) * 32;

    const int cv_i  = t >> 3;      // 0..31
    const int cv_jb = t & 7;
    const float* ev_row = ev + ((size_t)((b * 512 + i0 + cv_i) * 512)) * 3 + cv_jb * 24;
    const float* mk_row = mask + (size_t)(b * 512 + i0 + cv_i) * 512 + cv_jb * 8;
    const uint32_t cv_dst = (uint32_t)(cv_i * SM_ROW + cv_jb * 16);

    float acc[3][4][4];
#pragma unroll
    for (int c = 0; c < 3; ++c)
#pragma unroll
        for (int nt = 0; nt < 4; ++nt)
#pragma unroll
            for (int q = 0; q < 4; ++q) acc[c][nt][q] = 0.0f;

    const uint32_t a_lane = (uint32_t)((wm * 16 + (lane & 15)) * SM_ROW + (lane >> 4) * 16);
    uint32_t b_lane[2];
#pragma unroll
    for (int q = 0; q < 2; ++q) {
        int n = wn * 32 + q * 16 + (lane & 7) + ((lane >> 4) & 1) * 8;
        b_lane[q] = (uint32_t)(B_BASE + n * SM_ROW + ((lane >> 3) & 1) * 16);
    }

    auto issue_B = [&](int j0, int pb) {
#pragma unroll
        for (int p = t; p < 1024; p += 256) {
            int d = p >> 3, q = p & 7;
            const char* src = (const char*)g_hB
                + ((size_t)((b * 128 + d) * 512 + j0) * 2) + q * 16;
            CP_ASYNC16(smem_base + B_BASE + pb * B_BUF_STRIDE + d * SM_ROW + q * 16, src);
        }
        CP_COMMIT();
    };

    auto ldg_half = [&](int j0, int h, float4* rev, float4& rmk) {
        const float4* ep = (const float4*)(ev_row + (size_t)j0 * 3 + h * 12);
        rev[0] = ep[0]; rev[1] = ep[1]; rev[2] = ep[2];
        rmk = *(const float4*)(mk_row + j0 + h * 4);
    };

    auto convert_half = [&](int pa, int h, const float4* rev, const float4& rmk) {
        const float* evv = (const float*)rev;   // 12 floats: [j][c]
        float mv[4] = {rmk.x, rmk.y, rmk.z, rmk.w};
#pragma unroll
        for (int c = 0; c < 3; ++c) {
            uint32_t hi2[2], lo2[2];
#pragma unroll
            for (int pr = 0; pr < 2; ++pr) {
                float v0 = evv[(2 * pr)     * 3 + c] * mv[2 * pr];
                float v1 = evv[(2 * pr + 1) * 3 + c] * mv[2 * pr + 1];
                __half h0 = __float2half_rn(v0);
                __half h1 = __float2half_rn(v1);
                __half l0 = __float2half_rn(v0 - __half2float(h0));
                __half l1 = __float2half_rn(v1 - __half2float(h1));
                hi2[pr] = (uint32_t)__half_as_ushort(h0)
                        | ((uint32_t)__half_as_ushort(h1) << 16);
                lo2[pr] = (uint32_t)__half_as_ushort(l0)
                        | ((uint32_t)__half_as_ushort(l1) << 16);
            }
            char* dst = smc + pa * A_BUF_STRIDE + c * A_C_STRIDE + cv_dst + h * 8;
            *(uint2*)dst                = make_uint2(hi2[0], hi2[1]);
            *(uint2*)(dst + A_S_STRIDE) = make_uint2(lo2[0], lo2[1]);
        }
    };

    auto mma_kb = [&](int kb, int pa, int pb) {
        uint32_t afr[3][2][4];
        uint32_t bfr[2][4];
#pragma unroll
        for (int c = 0; c < 3; ++c)
#pragma unroll
            for (int sp = 0; sp < 2; ++sp)
                LDSM_X4(afr[c][sp], smem_base + pa * A_BUF_STRIDE + c * A_C_STRIDE
                                  + sp * A_S_STRIDE + a_lane + kb * 32);
#pragma unroll
        for (int q = 0; q < 2; ++q)
            LDSM_X4(bfr[q], smem_base + b_lane[q] + pb * B_BUF_STRIDE + kb * 32);
#pragma unroll
        for (int pass = 0; pass < 2; ++pass) {
#pragma unroll
            for (int c = 0; c < 3; ++c)
#pragma unroll
                for (int nt = 0; nt < 4; ++nt) {
                    uint32_t* bbv = bfr[nt >> 1];
                    MMA_F16(acc[c][nt], afr[c][pass],
                            bbv[(nt & 1) * 2], bbv[(nt & 1) * 2 + 1]);
                }
        }
    };

    // ---- prologue: fill A[0], B[0] for chunk 0
    {
        float4 rev[3]; float4 rmk;
        issue_B(0, 0);
        ldg_half(0, 0, rev, rmk);
        convert_half(0, 0, rev, rmk);
        ldg_half(0, 1, rev, rmk);
        convert_half(0, 1, rev, rmk);
        CP_WAIT(0);
        __syncthreads();
    }

#pragma unroll 1
    for (int ch = 0; ch < 8; ++ch) {
        const int p  = ch & 1;
        const int np = p ^ 1;
        const int nj = (ch + 1) * 64;
        float4 rev[3]; float4 rmk;

        if (ch < 7) {
            issue_B(nj, np);
            ldg_half(nj, 0, rev, rmk);
        }
        mma_kb(0, p, p);
        mma_kb(1, p, p);
        if (ch < 7) {
            convert_half(np, 0, rev, rmk);
            ldg_half(nj, 1, rev, rmk);
        }
        mma_kb(2, p, p);
        mma_kb(3, p, p);
        if (ch < 7) {
            convert_half(np, 1, rev, rmk);
        }
        CP_WAIT(0);
        __syncthreads();
    }

    // ---- epilogue: fragments -> out[b][i][c][d]
    const int r0 = i0 + wm * 16 + (lane >> 2);
    const int dq = wn * 32 + (lane & 3) * 2;
#pragma unroll
    for (int c = 0; c < 3; ++c) {
#pragma unroll
        for (int nt = 0; nt < 4; ++nt) {
            int d = dq + nt * 8;
            size_t o0 = ((size_t)(b * 512 + r0)     * 3 + c) * 128 + d;
            size_t o1 = ((size_t)(b * 512 + r0 + 8) * 3 + c) * 128 + d;
            *(float2*)(out + o0) = make_float2(acc[c][nt][0], acc[c][nt][1]);
            *(float2*)(out + o1) = make_float2(acc[c][nt][2], acc[c][nt][3]);
        }
    }
}

// ---------------------------------------------------------------------------
extern "C" void kernel_launch(void* const* d_in, const int* in_sizes, int n_in,
                              void* d_out, int out_size) {
    const float* s    = (const float*)d_in[0];   // (32,512,128)
    const float* ev   = (const float*)d_in[1];   // (32,512,512,3)
    const float* mask = (const float*)d_in[2];   // (32,512,512,1)
    const float* W1   = (const float*)d_in[3];   // (128,128)
    const float* b1   = (const float*)d_in[4];   // (128,)
    float* out = (float*)d_out;                  // (32,512,3,128)

    cudaFuncSetAttribute(k1_lin_ln_silu,
                         cudaFuncAttributeMaxDynamicSharedMemorySize, K1_SMEM);
    cudaFuncSetAttribute(k2_cfconv_mma,
                         cudaFuncAttributeMaxDynamicSharedMemorySize, K2_SMEM);

    k1_lin_ln_silu<<<(BB * NN) / 64, 256, K1_SMEM>>>(s, W1, b1);
    k2_cfconv_mma<<<BB * 16, 256, K2_SMEM>>>(ev, mask, out);
}

// round 15
// speedup vs baseline: 1.5245x; 1.2016x over previous
#include <cuda_runtime.h>
#include <cuda_fp16.h>
#include <math.h>
#include <stdint.h>

#define BB 32
#define NN 512
#define HH 128

// h as single f16 plane, [b][d][n] (transposed), row-contiguous in n. 4 MB.
__device__ __half g_hB[BB * HH * NN];

__device__ __forceinline__ uint32_t smem_u32(const void* p) {
    uint32_t a;
    asm("{ .reg .u64 t; cvta.to.shared.u64 t, %1; cvt.u32.u64 %0, t; }"
        : "=r"(a) : "l"(p));
    return a;
}

#define CP_ASYNC16(dst_u32, src_ptr) \
    asm volatile("cp.async.cg.shared.global [%0], [%1], 16;" \
                 :: "r"(dst_u32), "l"(src_ptr) : "memory")
#define CP_COMMIT() asm volatile("cp.async.commit_group;" ::: "memory")
#define CP_WAIT(n)  asm volatile("cp.async.wait_group %0;" :: "n"(n) : "memory")

#define LDSM_X4(r, addr) \
    asm volatile("ldmatrix.sync.aligned.m8n8.x4.shared.b16 {%0,%1,%2,%3}, [%4];" \
                 : "=r"((r)[0]), "=r"((r)[1]), "=r"((r)[2]), "=r"((r)[3]) \
                 : "r"(addr))

#define MMA_F16(acc, a, b0, b1) \
    asm volatile("mma.sync.aligned.m16n8k16.row.col.f32.f16.f16.f32 " \
                 "{%0,%1,%2,%3}, {%4,%5,%6,%7}, {%8,%9}, {%0,%1,%2,%3};" \
                 : "+f"((acc)[0]), "+f"((acc)[1]), "+f"((acc)[2]), "+f"((acc)[3]) \
                 : "r"((a)[0]), "r"((a)[1]), "r"((a)[2]), "r"((a)[3]), \
                   "r"(b0), "r"(b1))

// ---------------------------------------------------------------------------
// K1 (R14, measured good): h = silu(LN(s @ W1^T + b1)) via 3-pass split-f16 HMMA.
// 256 CTAs x 256 thr (8 warps, 4m x 2n); 64 rows/CTA; 2 CTAs/SM.
// ---------------------------------------------------------------------------
#define K1_ROWB 272
#define K1_WHI  0
#define K1_WLO  34816
#define K1_SHI  69632
#define K1_SLO  87040
#define K1_HP   69632
#define K1_TR   0
#define K1_SMEM 104448

__global__ void __launch_bounds__(256, 2)
k1_lin_ln_silu(const float* __restrict__ s,
               const float* __restrict__ W1,
               const float* __restrict__ b1) {
    extern __shared__ char smc[];
    const uint32_t smem_base = smem_u32(smc);
    const int t    = threadIdx.x;
    const int lane = t & 31;
    const int wid  = t >> 5;
    const int wm   = wid >> 1;     // 0..3: row subtile of 16
    const int wn   = wid & 1;      // 0..1: d subtile of 64
    const int row0 = blockIdx.x * 64;
    const int b    = blockIdx.x >> 3;
    const int n0   = (blockIdx.x & 7) * 64;

    // ---- convert W1 fp32 -> f16 hi/lo planes (direct from global, L2-hot)
#pragma unroll
    for (int k = 0; k < 32; ++k) {
        int u = t + k * 256;           // pair index 0..8191
        int d = u >> 6, kp = u & 63;
        float2 v = *(const float2*)&W1[u * 2];
        __half h0 = __float2half_rn(v.x), h1 = __float2half_rn(v.y);
        __half l0 = __float2half_rn(v.x - __half2float(h0));
        __half l1 = __float2half_rn(v.y - __half2float(h1));
        *(uint32_t*)(smc + K1_WHI + d * K1_ROWB + kp * 4) =
            (uint32_t)__half_as_ushort(h0) | ((uint32_t)__half_as_ushort(h1) << 16);
        *(uint32_t*)(smc + K1_WLO + d * K1_ROWB + kp * 4) =
            (uint32_t)__half_as_ushort(l0) | ((uint32_t)__half_as_ushort(l1) << 16);
    }
    // ---- convert s tile fp32 -> f16 hi/lo planes
#pragma unroll
    for (int k = 0; k < 16; ++k) {
        int u = t + k * 256;           // pair index 0..4095
        int r = u >> 6, kp = u & 63;
        float2 v = *(const float2*)&s[(size_t)row0 * 128 + u * 2];
        __half h0 = __float2half_rn(v.x), h1 = __float2half_rn(v.y);
        __half l0 = __float2half_rn(v.x - __half2float(h0));
        __half l1 = __float2half_rn(v.y - __half2float(h1));
        *(uint32_t*)(smc + K1_SHI + r * K1_ROWB + kp * 4) =
            (uint32_t)__half_as_ushort(h0) | ((uint32_t)__half_as_ushort(h1) << 16);
        *(uint32_t*)(smc + K1_SLO + r * K1_ROWB + kp * 4) =
            (uint32_t)__half_as_ushort(l0) | ((uint32_t)__half_as_ushort(l1) << 16);
    }
    __syncthreads();

    // ---- MMA: warp tile m16 x n64, K=128 over 8 kb-steps, 3 passes
    float acc[8][4];
#pragma unroll
    for (int nt = 0; nt < 8; ++nt)
#pragma unroll
        for (int q = 0; q < 4; ++q) acc[nt][q] = 0.0f;

    const uint32_t aaddr = smem_base + K1_SHI
        + (uint32_t)((wm * 16 + (lane & 15)) * K1_ROWB + (lane >> 4) * 16);
    uint32_t baddr[4];
#pragma unroll
    for (int q = 0; q < 4; ++q) {
        int n = wn * 64 + q * 16 + (lane & 7) + ((lane >> 4) & 1) * 8;
        baddr[q] = smem_base + K1_WHI
            + (uint32_t)(n * K1_ROWB + ((lane >> 3) & 1) * 16);
    }

#pragma unroll
    for (int kb = 0; kb < 8; ++kb) {
        uint32_t afr[2][4];
        LDSM_X4(afr[0], aaddr + kb * 32);                    // s hi
        LDSM_X4(afr[1], aaddr + (K1_SLO - K1_SHI) + kb * 32);// s lo
        uint32_t bfr[2][4][4];
#pragma unroll
        for (int sp = 0; sp < 2; ++sp)
#pragma unroll
            for (int q = 0; q < 4; ++q)
                LDSM_X4(bfr[sp][q], baddr[q] + sp * (K1_WLO - K1_WHI) + kb * 32);
#pragma unroll
        for (int pass = 0; pass < 3; ++pass) {
            const int as = (pass == 1) ? 1 : 0;
            const int bs = (pass == 2) ? 1 : 0;
#pragma unroll
            for (int nt = 0; nt < 8; ++nt) {
                uint32_t* bbv = bfr[bs][nt >> 1];
                MMA_F16(acc[nt], afr[as],
                        bbv[(nt & 1) * 2], bbv[(nt & 1) * 2 + 1]);
            }
        }
    }
    __syncthreads();           // all LDSM of s/W planes done

    // ---- fragments (+bias from global) -> HP (overlays SHI/SLO)
    float* hpf = (float*)(smc + K1_HP);
    {
        int r = wm * 16 + (lane >> 2);
#pragma unroll
        for (int nt = 0; nt < 8; ++nt) {
            int d = wn * 64 + (nt >> 1) * 16 + (nt & 1) * 8 + (lane & 3) * 2;
            float2 bb = *(const float2*)&b1[d];
            *(float2*)&hpf[r * 132 + d] =
                make_float2(acc[nt][0] + bb.x, acc[nt][1] + bb.y);
            *(float2*)&hpf[(r + 8) * 132 + d] =
                make_float2(acc[nt][2] + bb.x, acc[nt][3] + bb.y);
        }
    }
    __syncthreads();

    // ---- LN + SiLU + f16 -> TR (overlays WHI)
    uint32_t* tr = (uint32_t*)(smc + K1_TR);
    const float inv128 = 1.0f / 128.0f;
    const float4* hp4 = (const float4*)hpf;
#pragma unroll
    for (int rr = 0; rr < 8; ++rr) {
        int row = wid * 8 + rr;
        float4 x = hp4[row * 33 + lane];
        float sm = x.x + x.y + x.z + x.w;
        float sq = x.x * x.x + x.y * x.y + x.z * x.z + x.w * x.w;
#pragma unroll
        for (int o = 16; o > 0; o >>= 1) {
            sm += __shfl_xor_sync(0xFFFFFFFFu, sm, o);
            sq += __shfl_xor_sync(0xFFFFFFFFu, sq, o);
        }
        float mu  = sm * inv128;
        float var = sq * inv128 - mu * mu;
        float rs  = rsqrtf(var + 1e-5f);
        float y[4];
        y[0] = (x.x - mu) * rs; y[1] = (x.y - mu) * rs;
        y[2] = (x.z - mu) * rs; y[3] = (x.w - mu) * rs;
#pragma unroll
        for (int q = 0; q < 4; ++q) {
            float yv = y[q] / (1.0f + __expf(-y[q]));    // silu
            tr[(4 * lane + q) * 66 + row] =
                (uint32_t)__half_as_ushort(__float2half_rn(yv));
        }
    }
    __syncthreads();

    // ---- packed transposed store -> g_hB
#pragma unroll
    for (int k = 0; k < 16; ++k) {
        int u = t + k * 256;              // 0..4095
        int d = u >> 5, np = u & 31;
        uint2 tp = *(uint2*)&tr[d * 66 + 2 * np];
        uint32_t pk = (tp.x & 0xFFFFu) | (tp.y << 16);
        ((uint32_t*)g_hB)[((b * 128 + d) * 512 + n0) / 2 + np] = pk;
    }
}

// ---------------------------------------------------------------------------
// K2: single-pass f16 HMMA CFConv (A = mev rounded to f16; no lo split).
// grid: 32 b x 16 i-tiles (32 i) = 512 CTAs, 256 threads (8 warps 2m x 4n).
// smem (64512 B/CTA, 2+/SM):
//   A[2buf][3c][32 i][144B] = 27648 B
//   B[2buf][128 d][144B] @27648 = 36864 B
// R7 schedule: fill(ch+1) interleaved inside MMA(ch).
// ---------------------------------------------------------------------------
#define A_BUF_STRIDE 13824
#define A_C_STRIDE   4608
#define SM_ROW       144
#define B_BASE       27648
#define B_BUF_STRIDE 18432
#define K2_SMEM      64512

__global__ void __launch_bounds__(256, 2)
k2_cfconv_mma(const float* __restrict__ ev,
              const float* __restrict__ mask,
              float* __restrict__ out) {
    extern __shared__ char smc[];
    const uint32_t smem_base = smem_u32(smc);
    const int t    = threadIdx.x;
    const int lane = t & 31;
    const int wid  = t >> 5;
    const int wm   = wid >> 2;     // 0..1: i-subtile of 16
    const int wn   = wid & 3;      // 0..3: d-subtile of 32
    const int b    = blockIdx.x >> 4;
    const int i0   = (blockIdx.x & 15) * 32;

    const int cv_i  = t >> 3;      // 0..31
    const int cv_jb = t & 7;
    const float* ev_row = ev + ((size_t)((b * 512 + i0 + cv_i) * 512)) * 3 + cv_jb * 24;
    const float* mk_row = mask + (size_t)(b * 512 + i0 + cv_i) * 512 + cv_jb * 8;
    const uint32_t cv_dst = (uint32_t)(cv_i * SM_ROW + cv_jb * 16);

    float acc[3][4][4];
#pragma unroll
    for (int c = 0; c < 3; ++c)
#pragma unroll
        for (int nt = 0; nt < 4; ++nt)
#pragma unroll
            for (int q = 0; q < 4; ++q) acc[c][nt][q] = 0.0f;

    const uint32_t a_lane = (uint32_t)((wm * 16 + (lane & 15)) * SM_ROW + (lane >> 4) * 16);
    uint32_t b_lane[2];
#pragma unroll
    for (int q = 0; q < 2; ++q) {
        int n = wn * 32 + q * 16 + (lane & 7) + ((lane >> 4) & 1) * 8;
        b_lane[q] = (uint32_t)(B_BASE + n * SM_ROW + ((lane >> 3) & 1) * 16);
    }

    auto issue_B = [&](int j0, int pb) {
#pragma unroll
        for (int p = t; p < 1024; p += 256) {
            int d = p >> 3, q = p & 7;
            const char* src = (const char*)g_hB
                + ((size_t)((b * 128 + d) * 512 + j0) * 2) + q * 16;
            CP_ASYNC16(smem_base + B_BASE + pb * B_BUF_STRIDE + d * SM_ROW + q * 16, src);
        }
        CP_COMMIT();
    };

    auto ldg_half = [&](int j0, int h, float4* rev, float4& rmk) {
        const float4* ep = (const float4*)(ev_row + (size_t)j0 * 3 + h * 12);
        rev[0] = ep[0]; rev[1] = ep[1]; rev[2] = ep[2];
        rmk = *(const float4*)(mk_row + j0 + h * 4);
    };

    // convert one half into A[pa]: single f16 rounding of m*ev
    auto convert_half = [&](int pa, int h, const float4* rev, const float4& rmk) {
        const float* evv = (const float*)rev;   // 12 floats: [j][c]
        float mv[4] = {rmk.x, rmk.y, rmk.z, rmk.w};
#pragma unroll
        for (int c = 0; c < 3; ++c) {
            uint32_t hi2[2];
#pragma unroll
            for (int pr = 0; pr < 2; ++pr) {
                float v0 = evv[(2 * pr)     * 3 + c] * mv[2 * pr];
                float v1 = evv[(2 * pr + 1) * 3 + c] * mv[2 * pr + 1];
                __half h0 = __float2half_rn(v0);
                __half h1 = __float2half_rn(v1);
                hi2[pr] = (uint32_t)__half_as_ushort(h0)
                        | ((uint32_t)__half_as_ushort(h1) << 16);
            }
            char* dst = smc + pa * A_BUF_STRIDE + c * A_C_STRIDE + cv_dst + h * 8;
            *(uint2*)dst = make_uint2(hi2[0], hi2[1]);
        }
    };

    auto mma_kb = [&](int kb, int pa, int pb) {
        uint32_t afr[3][4];
        uint32_t bfr[2][4];
#pragma unroll
        for (int c = 0; c < 3; ++c)
            LDSM_X4(afr[c], smem_base + pa * A_BUF_STRIDE + c * A_C_STRIDE
                          + a_lane + kb * 32);
#pragma unroll
        for (int q = 0; q < 2; ++q)
            LDSM_X4(bfr[q], smem_base + b_lane[q] + pb * B_BUF_STRIDE + kb * 32);
#pragma unroll
        for (int c = 0; c < 3; ++c)
#pragma unroll
            for (int nt = 0; nt < 4; ++nt) {
                uint32_t* bbv = bfr[nt >> 1];
                MMA_F16(acc[c][nt], afr[c],
                        bbv[(nt & 1) * 2], bbv[(nt & 1) * 2 + 1]);
            }
    };

    // ---- prologue: fill A[0], B[0] for chunk 0
    {
        float4 rev[3]; float4 rmk;
        issue_B(0, 0);
        ldg_half(0, 0, rev, rmk);
        convert_half(0, 0, rev, rmk);
        ldg_half(0, 1, rev, rmk);
        convert_half(0, 1, rev, rmk);
        CP_WAIT(0);
        __syncthreads();
    }

#pragma unroll 1
    for (int ch = 0; ch < 8; ++ch) {
        const int p  = ch & 1;
        const int np = p ^ 1;
        const int nj = (ch + 1) * 64;
        float4 rev[3]; float4 rmk;

        if (ch < 7) {
            issue_B(nj, np);
            ldg_half(nj, 0, rev, rmk);
        }
        mma_kb(0, p, p);
        mma_kb(1, p, p);
        if (ch < 7) {
            convert_half(np, 0, rev, rmk);
            ldg_half(nj, 1, rev, rmk);
        }
        mma_kb(2, p, p);
        mma_kb(3, p, p);
        if (ch < 7) {
            convert_half(np, 1, rev, rmk);
        }
        CP_WAIT(0);
        __syncthreads();
    }

    // ---- epilogue: fragments -> out[b][i][c][d]
    const int r0 = i0 + wm * 16 + (lane >> 2);
    const int dq = wn * 32 + (lane & 3) * 2;
#pragma unroll
    for (int c = 0; c < 3; ++c) {
#pragma unroll
        for (int nt = 0; nt < 4; ++nt) {
            int d = dq + nt * 8;
            size_t o0 = ((size_t)(b * 512 + r0)     * 3 + c) * 128 + d;
            size_t o1 = ((size_t)(b * 512 + r0 + 8) * 3 + c) * 128 + d;
            *(float2*)(out + o0) = make_float2(acc[c][nt][0], acc[c][nt][1]);
            *(float2*)(out + o1) = make_float2(acc[c][nt][2], acc[c][nt][3]);
        }
    }
}

// ---------------------------------------------------------------------------
extern "C" void kernel_launch(void* const* d_in, const int* in_sizes, int n_in,
                              void* d_out, int out_size) {
    const float* s    = (const float*)d_in[0];   // (32,512,128)
    const float* ev   = (const float*)d_in[1];   // (32,512,512,3)
    const float* mask = (const float*)d_in[2];   // (32,512,512,1)
    const float* W1   = (const float*)d_in[3];   // (128,128)
    const float* b1   = (const float*)d_in[4];   // (128,)
    float* out = (float*)d_out;                  // (32,512,3,128)

    cudaFuncSetAttribute(k1_lin_ln_silu,
                         cudaFuncAttributeMaxDynamicSharedMemorySize, K1_SMEM);
    cudaFuncSetAttribute(k2_cfconv_mma,
                         cudaFuncAttributeMaxDynamicSharedMemorySize, K2_SMEM);

    k1_lin_ln_silu<<<(BB * NN) / 64, 256, K1_SMEM>>>(s, W1, b1);
    k2_cfconv_mma<<<BB * 16, 256, K2_SMEM>>>(ev, mask, out);
}